// round 15
// baseline (speedup 1.0000x reference)
#include <cuda_runtime.h>
#include <cuda_bf16.h>
#include <cuda_fp16.h>
#include <math.h>
#include <stdint.h>

#define BB 8
#define CC 64
#define OO 64
#define HH 128
#define WW 128
#define HWSZ (HH*WW)            // 16384
#define NPIX (BB*HWSZ)          // 131072
#define TPB 256

typedef unsigned long long ull;

// ---------------- scratch (allocation-free: __device__ globals) --------------
__device__ float4         g_cw4[(size_t)NPIX*9];    // per (p,k): 4 corner weights
__device__ int4           g_ci4[(size_t)NPIX*9];    // per (p,k): 4 clamped hw indices
__device__ float          g_xt[(size_t)NPIX*CC];    // [b][hw][c] (33.5 MB, L2-resident)
__device__ __half         g_Wf[9*64*64];            // main W fp16: [k][o][c] 128B rows
__device__ __nv_bfloat16  g_OMbh[9*32*64];          // off/mask W hi: [t][j(32)][c]
__device__ __nv_bfloat16  g_OMbl[9*32*64];          // off/mask W lo

// ---------------- packed f32x2 helpers ---------------------------------------
__device__ __forceinline__ ull pk2(float lo, float hi){
    ull r; asm("mov.b64 %0, {%1,%2};" : "=l"(r) : "f"(lo), "f"(hi)); return r;
}
__device__ __forceinline__ void upk2(ull v, float& lo, float& hi){
    asm("mov.b64 {%0,%1}, %2;" : "=f"(lo), "=f"(hi) : "l"(v));
}
__device__ __forceinline__ ull f2fma(ull a, ull b, ull c){
    ull d; asm("fma.rn.f32x2 %0, %1, %2, %3;" : "=l"(d) : "l"(a), "l"(b), "l"(c)); return d;
}
__device__ __forceinline__ ull ldg2(const float* p){
    ull v; asm("ld.global.nc.b64 %0, [%1];" : "=l"(v) : "l"(p)); return v;
}
__device__ __forceinline__ uint32_t smem_u32(const void* p){
    uint32_t a;
    asm("{ .reg .u64 t; cvta.to.shared.u64 t, %1; cvt.u32.u64 %0, t; }" : "=r"(a) : "l"(p));
    return a;
}
__device__ __forceinline__ void ldsm4(uint32_t* r, uint32_t addr){
    asm volatile("ldmatrix.sync.aligned.m8n8.x4.shared.b16 {%0,%1,%2,%3}, [%4];"
        : "=r"(r[0]), "=r"(r[1]), "=r"(r[2]), "=r"(r[3]) : "r"(addr));
}
__device__ __forceinline__ void hmma_bf(float* d, const uint32_t* a, uint32_t b0, uint32_t b1){
    asm volatile("mma.sync.aligned.m16n8k16.row.col.f32.bf16.bf16.f32 "
        "{%0,%1,%2,%3}, {%4,%5,%6,%7}, {%8,%9}, {%0,%1,%2,%3};"
        : "+f"(d[0]), "+f"(d[1]), "+f"(d[2]), "+f"(d[3])
        : "r"(a[0]), "r"(a[1]), "r"(a[2]), "r"(a[3]), "r"(b0), "r"(b1));
}
__device__ __forceinline__ void hmma_f16(float* d, const uint32_t* a, uint32_t b0, uint32_t b1){
    asm volatile("mma.sync.aligned.m16n8k16.row.col.f32.f16.f16.f32 "
        "{%0,%1,%2,%3}, {%4,%5,%6,%7}, {%8,%9}, {%0,%1,%2,%3};"
        : "+f"(d[0]), "+f"(d[1]), "+f"(d[2]), "+f"(d[3])
        : "r"(a[0]), "r"(a[1]), "r"(a[2]), "r"(a[3]), "r"(b0), "r"(b1));
}
// packed fp32x2 -> bf16x2 hi + bf16x2 lo (residual)
__device__ __forceinline__ void cvt_hilo_bf(ull v, uint32_t& ph, uint32_t& pl){
    float f0,f1; upk2(v,f0,f1);
    asm("cvt.rn.bf16x2.f32 %0, %1, %2;" : "=r"(ph) : "f"(f1), "f"(f0));
    uint32_t h0b = ph<<16, h1b = ph & 0xffff0000u;
    ull hp;  asm("mov.b64 %0, {%1,%2};" : "=l"(hp) : "r"(h0b), "r"(h1b));
    ull lo2; asm("sub.rn.f32x2 %0, %1, %2;" : "=l"(lo2) : "l"(v), "l"(hp));
    float g0,g1; upk2(lo2,g0,g1);
    asm("cvt.rn.bf16x2.f32 %0, %1, %2;" : "=r"(pl) : "f"(g1), "f"(g0));
}
// packed fp32x2 -> fp16x2 hi + fp16x2 lo (residual)
__device__ __forceinline__ void cvt_hilo_f16(ull v, uint32_t& ph, uint32_t& pl){
    float f0,f1; upk2(v,f0,f1);
    __half2 h2 = __floats2half2_rn(f0,f1);
    float2 hf = __half22float2(h2);
    __half2 l2 = __floats2half2_rn(f0-hf.x, f1-hf.y);
    ph = *(uint32_t*)&h2;
    pl = *(uint32_t*)&l2;
}

// ---------------- prep: main W fp16; off/mask W bf16 hi/lo --------------------
__global__ void k_prep(const float* __restrict__ wm,
                       const float* __restrict__ wo,
                       const float* __restrict__ wk){
    int i = blockIdx.x*TPB + threadIdx.x;
    if (i < 9*64*64){
        int k = i >> 12; int o = (i >> 6) & 63; int c = i & 63;
        g_Wf[i] = __float2half(wm[(o*CC + c)*9 + k]);
    }
    int j2 = i - 9*64*64;
    if (j2 >= 0 && j2 < 9*32*64){
        int tp = j2 >> 11; int j = (j2 >> 6) & 31; int c = j2 & 63;
        float v = 0.f;
        if (j < 18)      v = wo[(j*CC + c)*9 + tp];
        else if (j < 27) v = wk[((j-18)*CC + c)*9 + tp];
        __nv_bfloat16 h = __float2bfloat16(v);
        float r = v - __bfloat162float(h);
        g_OMbh[j2] = h;
        g_OMbl[j2] = __float2bfloat16(r);
    }
}

// ---------------- P0: x [b][c][hw] -> g_xt [b][hw][c] -------------------------
__global__ void k_xt(const float* __restrict__ x){
    __shared__ float t[32][33];
    int b  = blockIdx.z;
    int c0 = blockIdx.y*32;
    int hw0= blockIdx.x*32;
    const float* xb = x + ((size_t)b*CC + c0)*HWSZ + hw0;
    for (int i = threadIdx.y; i < 32; i += 8)
        t[i][threadIdx.x] = xb[(size_t)i*HWSZ + threadIdx.x];
    __syncthreads();
    float* xtb = g_xt + ((size_t)b*HWSZ + hw0)*CC + c0;
    for (int i = threadIdx.y; i < 32; i += 8)
        xtb[(size_t)i*CC + threadIdx.x] = t[threadIdx.x][i];
}

// ---- P1: offset+mask conv as bf16 HMMA GEMM (unchanged from R14) ------------
__global__ void __launch_bounds__(TPB)
k_om(const float* __restrict__ boff, const float* __restrict__ bmsk){
    __shared__ __align__(16) uint4 smem[2880];   // 46080 B
    uint32_t* wA = (uint32_t*)smem;

    int t = threadIdx.x, l = t & 31, w = t >> 5;
    int p0 = blockIdx.x*128;
    int b  = p0 >> 14;
    const float* xtb = g_xt + (size_t)b*HWSZ*CC;

    int m0 = (w >> 1)*32;
    int n0 = (w & 1)*16;

    uint32_t aBase = smem_u32(smem);

    float acc[2][2][4];
    #pragma unroll
    for (int i=0;i<2;i++)
        #pragma unroll
        for (int j=0;j<2;j++)
            #pragma unroll
            for (int q=0;q<4;q++) acc[i][j][q] = 0.f;

    int a_row = (l & 7) + ((l >> 3) & 1)*8;
    int a_kb  = l >> 4;
    int b_row = (l & 7) + (l >> 4)*8;
    int b_kb  = (l >> 3) & 1;
    int brow = t >> 3, bu = t & 7;

    for (int tap=0; tap<9; tap++){
        __syncthreads();
        smem[2304 + brow*9 + bu] = __ldg((const uint4*)(g_OMbh + (size_t)tap*2048 + brow*64) + bu);
        smem[2592 + brow*9 + bu] = __ldg((const uint4*)(g_OMbl + (size_t)tap*2048 + brow*64) + bu);
        int dh = tap/3 - 1, dw = tap%3 - 1;
        #pragma unroll
        for (int j=0;j<16;j++){
            int px = w*16 + j;
            int hw = (p0 + px) & (HWSZ-1);
            int h = hw >> 7, wc = hw & (WW-1);
            ull v = 0ull;
            if ((unsigned)(h+dh) < HH && (unsigned)(wc+dw) < WW)
                v = ldg2(xtb + (size_t)(hw + dh*WW + dw)*CC + 2*l);
            uint32_t ph, pl; cvt_hilo_bf(v, ph, pl);
            wA[px*36 + l]        = ph;
            wA[4608 + px*36 + l] = pl;
        }
        __syncthreads();

        #pragma unroll
        for (int ks=0; ks<4; ks++){
            uint32_t ah[2][4], al[2][4], bh[4], bl[4];
            #pragma unroll
            for (int mf=0; mf<2; mf++){
                uint32_t offA = (uint32_t)((m0 + mf*16 + a_row)*9 + ks*2 + a_kb)*16u;
                ldsm4(ah[mf], aBase + offA);
                ldsm4(al[mf], aBase + 18432u + offA);
            }
            {
                uint32_t offB = (uint32_t)((n0 + b_row)*9 + ks*2 + b_kb)*16u;
                ldsm4(bh, aBase + 36864u + offB);
                ldsm4(bl, aBase + 41472u + offB);
            }
            #pragma unroll
            for (int mf=0; mf<2; mf++){
                #pragma unroll
                for (int nf=0; nf<2; nf++){
                    hmma_bf(acc[mf][nf], ah[mf], bh[nf*2], bh[nf*2+1]);
                    hmma_bf(acc[mf][nf], ah[mf], bl[nf*2], bl[nf*2+1]);
                    hmma_bf(acc[mf][nf], al[mf], bh[nf*2], bh[nf*2+1]);
                }
            }
        }
    }

    __syncthreads();
    float* st = (float*)smem;
    {
        int group = l >> 2, tid4 = l & 3;
        #pragma unroll
        for (int mf=0; mf<2; mf++){
            int r0 = m0 + mf*16 + group;
            #pragma unroll
            for (int nf=0; nf<2; nf++){
                int o = n0 + nf*8 + 2*tid4;
                if (o < 28){
                    st[r0*28 + o]       = acc[mf][nf][0];
                    st[r0*28 + o+1]     = acc[mf][nf][1];
                    st[(r0+8)*28 + o]   = acc[mf][nf][2];
                    st[(r0+8)*28 + o+1] = acc[mf][nf][3];
                }
            }
        }
    }
    __syncthreads();
    if (t < 128){
        int p  = p0 + t;
        int hw = p & (HWSZ-1);
        int h  = hw >> 7;
        int wp = hw & (WW-1);
        const float* row = st + t*28;
        #pragma unroll
        for (int k=0;k<9;k++){
            float dy   = row[2*k]   + boff[2*k];
            float dx   = row[2*k+1] + boff[2*k+1];
            float mraw = row[18+k]  + bmsk[k];
            float mk = 1.f/(1.f + expf(-mraw));

            float py = dy + (float)(h + k/3 - 1);
            float px = dx + (float)(wp + k%3 - 1);
            float y0f = floorf(py), x0f = floorf(px);
            float ly = py - y0f, lx = px - x0f;
            int y0 = (int)y0f, x0 = (int)x0f;
            int y1 = y0 + 1,   x1 = x0 + 1;

            float vy0 = (y0>=0 && y0<HH) ? 1.f : 0.f;
            float vy1 = (y1>=0 && y1<HH) ? 1.f : 0.f;
            float vx0 = (x0>=0 && x0<WW) ? 1.f : 0.f;
            float vx1 = (x1>=0 && x1<WW) ? 1.f : 0.f;

            float w00 = (1.f-ly)*(1.f-lx)*vy0*vx0*mk;
            float w01 = (1.f-ly)*lx      *vy0*vx1*mk;
            float w10 = ly      *(1.f-lx)*vy1*vx0*mk;
            float w11 = ly      *lx      *vy1*vx1*mk;

            int y0c = min(max(y0,0),HH-1), y1c = min(max(y1,0),HH-1);
            int x0c = min(max(x0,0),WW-1), x1c = min(max(x1,0),WW-1);

            g_cw4[(size_t)p*9 + k] = make_float4(w00,w01,w10,w11);
            g_ci4[(size_t)p*9 + k] = make_int4(y0c*WW+x0c, y0c*WW+x1c,
                                               y1c*WW+x0c, y1c*WW+x1c);
        }
    }
}

// ---- P2: fused gather + fp16 2-pass HMMA, double-buffered A -----------------
// CTA = 64 px x 64 o, 8 warps (warp tile 32px x 16o). A(k+1) gathered into the
// other buffer while mma(k) runs; B reloaded per k under the bottom barrier.
// smem: bufA0 hi|lo [0,1152), bufA1 hi|lo [1152,2304), B [2304,2880) = 46080 B.
__global__ void __launch_bounds__(TPB)
k_fuse(float* __restrict__ out){
    __shared__ __align__(16) uint4 smem[2880];
    uint32_t* wA = (uint32_t*)smem;
    uint4* sBw = smem + 2304;

    int t = threadIdx.x, l = t & 31, w = t >> 5;
    int p0 = blockIdx.x*64;
    int b  = p0 >> 14;
    int hw0= p0 & (HWSZ-1);
    const float* xtb = g_xt + (size_t)b*HWSZ*CC;

    int m0 = (w & 1)*32;
    int n0 = (w >> 1)*16;

    uint32_t aBase = smem_u32(smem);
    uint32_t bBase = aBase + 2304u*16u;

    float acc[2][2][4];
    #pragma unroll
    for (int i=0;i<2;i++)
        #pragma unroll
        for (int j=0;j<2;j++)
            #pragma unroll
            for (int q=0;q<4;q++) acc[i][j][q] = 0.f;

    int a_row = (l & 7) + ((l >> 3) & 1)*8;
    int a_kb  = l >> 4;
    int b_row = (l & 7) + (l >> 4)*8;
    int b_kb  = (l >> 3) & 1;
    int brow = t >> 2, bq2 = (t & 3)*2;

    // ---- preload: gather(0) into buf0; B(0)
    #pragma unroll
    for (int j=0;j<8;j++){
        int px = w*8 + j;
        size_t pk = (size_t)(p0+px)*9;
        float4 wq = __ldg(&g_cw4[pk]);
        int4   iq = __ldg(&g_ci4[pk]);
        ull v;
        v = f2fma(pk2(wq.x,wq.x), ldg2(xtb + (size_t)iq.x*CC + 2*l), 0ull);
        v = f2fma(pk2(wq.y,wq.y), ldg2(xtb + (size_t)iq.y*CC + 2*l), v);
        v = f2fma(pk2(wq.z,wq.z), ldg2(xtb + (size_t)iq.z*CC + 2*l), v);
        v = f2fma(pk2(wq.w,wq.w), ldg2(xtb + (size_t)iq.w*CC + 2*l), v);
        uint32_t ph, pl; cvt_hilo_f16(v, ph, pl);
        wA[px*36 + l]        = ph;
        wA[2304 + px*36 + l] = pl;
    }
    {
        const uint4* gB = (const uint4*)(g_Wf + 0 + brow*64);
        #pragma unroll
        for (int u=0;u<2;u++) sBw[brow*9 + bq2 + u] = __ldg(gB + bq2 + u);
    }

    for (int kc=0; kc<9; kc++){
        int buf = kc & 1;
        __syncthreads();          // A(kc) + B(kc) visible; other buf free

        // ---- gather(kc+1) into the other buffer (overlaps mma across warps)
        if (kc < 8){
            int ob = buf ^ 1;
            #pragma unroll
            for (int j=0;j<8;j++){
                int px = w*8 + j;
                size_t pk = (size_t)(p0+px)*9 + kc + 1;
                float4 wq = __ldg(&g_cw4[pk]);
                int4   iq = __ldg(&g_ci4[pk]);
                ull v;
                v = f2fma(pk2(wq.x,wq.x), ldg2(xtb + (size_t)iq.x*CC + 2*l), 0ull);
                v = f2fma(pk2(wq.y,wq.y), ldg2(xtb + (size_t)iq.y*CC + 2*l), v);
                v = f2fma(pk2(wq.z,wq.z), ldg2(xtb + (size_t)iq.z*CC + 2*l), v);
                v = f2fma(pk2(wq.w,wq.w), ldg2(xtb + (size_t)iq.w*CC + 2*l), v);
                uint32_t ph, pl; cvt_hilo_f16(v, ph, pl);
                wA[ob*4608 + px*36 + l]        = ph;
                wA[ob*4608 + 2304 + px*36 + l] = pl;
            }
        }

        // ---- mma(kc): 2-pass fp16 (x_hi*W + x_lo*W)
        uint32_t aHi = aBase + (uint32_t)buf*18432u;
        uint32_t aLo = aHi + 9216u;
        #pragma unroll
        for (int ks=0; ks<4; ks++){
            uint32_t ah[2][4], al[2][4], bw[4];
            #pragma unroll
            for (int mf=0; mf<2; mf++){
                uint32_t off = (uint32_t)((m0 + mf*16 + a_row)*9 + ks*2 + a_kb)*16u;
                ldsm4(ah[mf], aHi + off);
                ldsm4(al[mf], aLo + off);
            }
            {
                uint32_t off = (uint32_t)((n0 + b_row)*9 + ks*2 + b_kb)*16u;
                ldsm4(bw, bBase + off);
            }
            #pragma unroll
            for (int mf=0; mf<2; mf++){
                #pragma unroll
                for (int nf=0; nf<2; nf++){
                    hmma_f16(acc[mf][nf], ah[mf], bw[nf*2], bw[nf*2+1]);
                    hmma_f16(acc[mf][nf], al[mf], bw[nf*2], bw[nf*2+1]);
                }
            }
        }

        __syncthreads();          // everyone done reading B(kc)
        if (kc < 8){
            const uint4* gB = (const uint4*)(g_Wf + (size_t)(kc+1)*4096 + brow*64);
            #pragma unroll
            for (int u=0;u<2;u++) sBw[brow*9 + bq2 + u] = __ldg(gB + bq2 + u);
        }
    }

    // ---- epilogue: stage [o][px pad68], coalesced float4 stores --------------
    __syncthreads();
    float* st = (float*)smem;
    {
        int group = l >> 2, tid4 = l & 3;
        #pragma unroll
        for (int mf=0; mf<2; mf++){
            int r0 = m0 + mf*16 + group;
            #pragma unroll
            for (int nf=0; nf<2; nf++){
                int o = n0 + nf*8 + 2*tid4;
                st[(size_t)o    *68 + r0    ] = acc[mf][nf][0];
                st[(size_t)(o+1)*68 + r0    ] = acc[mf][nf][1];
                st[(size_t)o    *68 + r0 + 8] = acc[mf][nf][2];
                st[(size_t)(o+1)*68 + r0 + 8] = acc[mf][nf][3];
            }
        }
    }
    __syncthreads();
    #pragma unroll
    for (int q=0;q<4;q++){
        int o   = q*16 + w*2 + (l >> 4);
        int px4 = (l & 15)*4;
        float4 v = *(float4*)&st[(size_t)o*68 + px4];
        *(float4*)(out + ((size_t)(b*OO + o))*HWSZ + hw0 + px4) = v;
    }
}

// ---------------- launch ------------------------------------------------------
extern "C" void kernel_launch(void* const* d_in, const int* in_sizes, int n_in,
                              void* d_out, int out_size){
    const float* x        = (const float*)d_in[0];
    const float* w_main   = (const float*)d_in[1];
    const float* w_offset = (const float*)d_in[2];
    const float* b_offset = (const float*)d_in[3];
    const float* w_mask   = (const float*)d_in[4];
    const float* b_mask   = (const float*)d_in[5];
    float* out = (float*)d_out;

    int prep_n = 9*64*64 + 9*32*64;
    k_prep<<<(prep_n + TPB-1)/TPB, TPB>>>(w_main, w_offset, w_mask);
    dim3 gx(HWSZ/32, CC/32, BB);
    k_xt<<<gx, dim3(32,8)>>>(x);
    k_om<<<NPIX/128, TPB>>>(b_offset, b_mask);
    k_fuse<<<NPIX/64, TPB>>>(out);
}

// round 16
// speedup vs baseline: 1.0143x; 1.0143x over previous
#include <cuda_runtime.h>
#include <cuda_bf16.h>
#include <math.h>
#include <stdint.h>

#define BB 8
#define CC 64
#define OO 64
#define HH 128
#define WW 128
#define HWSZ (HH*WW)            // 16384
#define NPIX (BB*HWSZ)          // 131072
#define TPB 256

typedef unsigned long long ull;

// ---------------- scratch (allocation-free: __device__ globals) --------------
__device__ float4         g_cw4[(size_t)NPIX*9];    // per (p,k): 4 corner weights
__device__ int4           g_ci4[(size_t)NPIX*9];    // per (p,k): 4 clamped hw indices
__device__ float          g_xt[(size_t)NPIX*CC];    // [b][hw][c] (33.5 MB, L2-resident)
__device__ __nv_bfloat16  g_Wbh[9*64*64];           // main W hi: [k][o][c] 128B rows
__device__ __nv_bfloat16  g_Wbl[9*64*64];           // main W lo
__device__ __nv_bfloat16  g_OMbh[9*32*64];          // off/mask W hi: [t][j(32)][c]
__device__ __nv_bfloat16  g_OMbl[9*32*64];          // off/mask W lo

// ---------------- packed f32x2 helpers ---------------------------------------
__device__ __forceinline__ ull pk2(float lo, float hi){
    ull r; asm("mov.b64 %0, {%1,%2};" : "=l"(r) : "f"(lo), "f"(hi)); return r;
}
__device__ __forceinline__ void upk2(ull v, float& lo, float& hi){
    asm("mov.b64 {%0,%1}, %2;" : "=f"(lo), "=f"(hi) : "l"(v));
}
__device__ __forceinline__ ull f2fma(ull a, ull b, ull c){
    ull d; asm("fma.rn.f32x2 %0, %1, %2, %3;" : "=l"(d) : "l"(a), "l"(b), "l"(c)); return d;
}
__device__ __forceinline__ ull ldg2(const float* p){
    ull v; asm("ld.global.nc.b64 %0, [%1];" : "=l"(v) : "l"(p)); return v;
}
__device__ __forceinline__ uint32_t smem_u32(const void* p){
    uint32_t a;
    asm("{ .reg .u64 t; cvta.to.shared.u64 t, %1; cvt.u32.u64 %0, t; }" : "=r"(a) : "l"(p));
    return a;
}
__device__ __forceinline__ void ldsm4(uint32_t* r, uint32_t addr){
    asm volatile("ldmatrix.sync.aligned.m8n8.x4.shared.b16 {%0,%1,%2,%3}, [%4];"
        : "=r"(r[0]), "=r"(r[1]), "=r"(r[2]), "=r"(r[3]) : "r"(addr));
}
__device__ __forceinline__ void hmma(float* d, const uint32_t* a, uint32_t b0, uint32_t b1){
    asm volatile("mma.sync.aligned.m16n8k16.row.col.f32.bf16.bf16.f32 "
        "{%0,%1,%2,%3}, {%4,%5,%6,%7}, {%8,%9}, {%0,%1,%2,%3};"
        : "+f"(d[0]), "+f"(d[1]), "+f"(d[2]), "+f"(d[3])
        : "r"(a[0]), "r"(a[1]), "r"(a[2]), "r"(a[3]), "r"(b0), "r"(b1));
}
// packed fp32x2 -> bf16x2 hi + bf16x2 lo (residual), 6 instrs
__device__ __forceinline__ void cvt_hilo(ull v, uint32_t& ph, uint32_t& pl){
    float f0,f1; upk2(v,f0,f1);
    asm("cvt.rn.bf16x2.f32 %0, %1, %2;" : "=r"(ph) : "f"(f1), "f"(f0));
    uint32_t h0b = ph<<16, h1b = ph & 0xffff0000u;
    ull hp;  asm("mov.b64 %0, {%1,%2};" : "=l"(hp) : "r"(h0b), "r"(h1b));
    ull lo2; asm("sub.rn.f32x2 %0, %1, %2;" : "=l"(lo2) : "l"(v), "l"(hp));
    float g0,g1; upk2(lo2,g0,g1);
    asm("cvt.rn.bf16x2.f32 %0, %1, %2;" : "=r"(pl) : "f"(g1), "f"(g0));
}

// ---------------- prep: main W + off/mask W -> bf16 hi/lo ---------------------
__global__ void k_prep(const float* __restrict__ wm,
                       const float* __restrict__ wo,
                       const float* __restrict__ wk){
    int i = blockIdx.x*TPB + threadIdx.x;
    if (i < 9*64*64){
        int k = i >> 12; int o = (i >> 6) & 63; int c = i & 63;
        float w = wm[(o*CC + c)*9 + k];
        __nv_bfloat16 h = __float2bfloat16(w);
        float r = w - __bfloat162float(h);
        g_Wbh[i] = h;
        g_Wbl[i] = __float2bfloat16(r);
    }
    int j2 = i - 9*64*64;
    if (j2 >= 0 && j2 < 9*32*64){
        int tp = j2 >> 11; int j = (j2 >> 6) & 31; int c = j2 & 63;
        float v = 0.f;
        if (j < 18)      v = wo[(j*CC + c)*9 + tp];
        else if (j < 27) v = wk[((j-18)*CC + c)*9 + tp];
        __nv_bfloat16 h = __float2bfloat16(v);
        float r = v - __bfloat162float(h);
        g_OMbh[j2] = h;
        g_OMbl[j2] = __float2bfloat16(r);
    }
}

// ---------------- P0: x [b][c][hw] -> g_xt [b][hw][c] -------------------------
__global__ void k_xt(const float* __restrict__ x){
    __shared__ float t[32][33];
    int b  = blockIdx.z;
    int c0 = blockIdx.y*32;
    int hw0= blockIdx.x*32;
    const float* xb = x + ((size_t)b*CC + c0)*HWSZ + hw0;
    for (int i = threadIdx.y; i < 32; i += 8)
        t[i][threadIdx.x] = xb[(size_t)i*HWSZ + threadIdx.x];
    __syncthreads();
    float* xtb = g_xt + ((size_t)b*HWSZ + hw0)*CC + c0;
    for (int i = threadIdx.y; i < 32; i += 8)
        xtb[(size_t)i*CC + threadIdx.x] = t[threadIdx.x][i];
}

// ---- P1: offset+mask conv as bf16 HMMA GEMM (R14, proven) -------------------
__global__ void __launch_bounds__(TPB)
k_om(const float* __restrict__ boff, const float* __restrict__ bmsk){
    __shared__ __align__(16) uint4 smem[2880];   // 46080 B
    uint32_t* wA = (uint32_t*)smem;

    int t = threadIdx.x, l = t & 31, w = t >> 5;
    int p0 = blockIdx.x*128;
    int b  = p0 >> 14;
    const float* xtb = g_xt + (size_t)b*HWSZ*CC;

    int m0 = (w >> 1)*32;
    int n0 = (w & 1)*16;

    uint32_t aBase = smem_u32(smem);

    float acc[2][2][4];
    #pragma unroll
    for (int i=0;i<2;i++)
        #pragma unroll
        for (int j=0;j<2;j++)
            #pragma unroll
            for (int q=0;q<4;q++) acc[i][j][q] = 0.f;

    int a_row = (l & 7) + ((l >> 3) & 1)*8;
    int a_kb  = l >> 4;
    int b_row = (l & 7) + (l >> 4)*8;
    int b_kb  = (l >> 3) & 1;
    int brow = t >> 3, bu = t & 7;

    for (int tap=0; tap<9; tap++){
        __syncthreads();
        smem[2304 + brow*9 + bu] = __ldg((const uint4*)(g_OMbh + (size_t)tap*2048 + brow*64) + bu);
        smem[2592 + brow*9 + bu] = __ldg((const uint4*)(g_OMbl + (size_t)tap*2048 + brow*64) + bu);
        int dh = tap/3 - 1, dw = tap%3 - 1;
        #pragma unroll
        for (int j=0;j<16;j++){
            int px = w*16 + j;
            int hw = (p0 + px) & (HWSZ-1);
            int h = hw >> 7, wc = hw & (WW-1);
            ull v = 0ull;
            if ((unsigned)(h+dh) < HH && (unsigned)(wc+dw) < WW)
                v = ldg2(xtb + (size_t)(hw + dh*WW + dw)*CC + 2*l);
            uint32_t ph, pl; cvt_hilo(v, ph, pl);
            wA[px*36 + l]        = ph;
            wA[4608 + px*36 + l] = pl;
        }
        __syncthreads();

        #pragma unroll
        for (int ks=0; ks<4; ks++){
            uint32_t ah[2][4], al[2][4], bh[4], bl[4];
            #pragma unroll
            for (int mf=0; mf<2; mf++){
                uint32_t offA = (uint32_t)((m0 + mf*16 + a_row)*9 + ks*2 + a_kb)*16u;
                ldsm4(ah[mf], aBase + offA);
                ldsm4(al[mf], aBase + 18432u + offA);
            }
            {
                uint32_t offB = (uint32_t)((n0 + b_row)*9 + ks*2 + b_kb)*16u;
                ldsm4(bh, aBase + 36864u + offB);
                ldsm4(bl, aBase + 41472u + offB);
            }
            #pragma unroll
            for (int mf=0; mf<2; mf++){
                #pragma unroll
                for (int nf=0; nf<2; nf++){
                    hmma(acc[mf][nf], ah[mf], bh[nf*2], bh[nf*2+1]);
                    hmma(acc[mf][nf], ah[mf], bl[nf*2], bl[nf*2+1]);
                    hmma(acc[mf][nf], al[mf], bh[nf*2], bh[nf*2+1]);
                }
            }
        }
    }

    __syncthreads();
    float* st = (float*)smem;
    {
        int group = l >> 2, tid4 = l & 3;
        #pragma unroll
        for (int mf=0; mf<2; mf++){
            int r0 = m0 + mf*16 + group;
            #pragma unroll
            for (int nf=0; nf<2; nf++){
                int o = n0 + nf*8 + 2*tid4;
                if (o < 28){
                    st[r0*28 + o]       = acc[mf][nf][0];
                    st[r0*28 + o+1]     = acc[mf][nf][1];
                    st[(r0+8)*28 + o]   = acc[mf][nf][2];
                    st[(r0+8)*28 + o+1] = acc[mf][nf][3];
                }
            }
        }
    }
    __syncthreads();
    if (t < 128){
        int p  = p0 + t;
        int hw = p & (HWSZ-1);
        int h  = hw >> 7;
        int wp = hw & (WW-1);
        const float* row = st + t*28;
        #pragma unroll
        for (int k=0;k<9;k++){
            float dy   = row[2*k]   + boff[2*k];
            float dx   = row[2*k+1] + boff[2*k+1];
            float mraw = row[18+k]  + bmsk[k];
            float mk = 1.f/(1.f + expf(-mraw));

            float py = dy + (float)(h + k/3 - 1);
            float px = dx + (float)(wp + k%3 - 1);
            float y0f = floorf(py), x0f = floorf(px);
            float ly = py - y0f, lx = px - x0f;
            int y0 = (int)y0f, x0 = (int)x0f;
            int y1 = y0 + 1,   x1 = x0 + 1;

            float vy0 = (y0>=0 && y0<HH) ? 1.f : 0.f;
            float vy1 = (y1>=0 && y1<HH) ? 1.f : 0.f;
            float vx0 = (x0>=0 && x0<WW) ? 1.f : 0.f;
            float vx1 = (x1>=0 && x1<WW) ? 1.f : 0.f;

            float w00 = (1.f-ly)*(1.f-lx)*vy0*vx0*mk;
            float w01 = (1.f-ly)*lx      *vy0*vx1*mk;
            float w10 = ly      *(1.f-lx)*vy1*vx0*mk;
            float w11 = ly      *lx      *vy1*vx1*mk;

            int y0c = min(max(y0,0),HH-1), y1c = min(max(y1,0),HH-1);
            int x0c = min(max(x0,0),WW-1), x1c = min(max(x1,0),WW-1);

            g_cw4[(size_t)p*9 + k] = make_float4(w00,w01,w10,w11);
            g_ci4[(size_t)p*9 + k] = make_int4(y0c*WW+x0c, y0c*WW+x1c,
                                               y1c*WW+x0c, y1c*WW+x1c);
        }
    }
}

// ---- P2: fused gather + HMMA, CTA=128px x 64o, warp tile 32px x 32o ---------
// bf16 3-pass, R11 k_mma fragment/epilogue layout + R14 gather. Dynamic smem:
// Ahi 1152 | Alo 1152 | Bh 576 | Bl 576 uint4 = 55296 B.
#define FUSE_SMEM 55296
__global__ void __launch_bounds__(TPB)
k_fuse(float* __restrict__ out){
    extern __shared__ __align__(16) uint4 smem[];
    uint32_t* wA = (uint32_t*)smem;

    int t = threadIdx.x, l = t & 31, w = t >> 5;
    int p0 = blockIdx.x*128;
    int b  = p0 >> 14;
    int hw0= p0 & (HWSZ-1);
    const float* xtb = g_xt + (size_t)b*HWSZ*CC;

    int m0 = (w & 3)*32;     // 4 m-tiles of 32 px (each read by 2 warps)
    int n0 = (w >> 2)*32;    // 2 n-tiles of 32 o  (each read by 4 warps)

    uint32_t aBase  = smem_u32(smem);
    uint32_t alBase = aBase + 18432u;
    uint32_t bhBase = aBase + 36864u;
    uint32_t blBase = aBase + 46080u;

    float acc[2][4][4];
    #pragma unroll
    for (int i=0;i<2;i++)
        #pragma unroll
        for (int j=0;j<4;j++)
            #pragma unroll
            for (int q=0;q<4;q++) acc[i][j][q] = 0.f;

    int a_row = (l & 7) + ((l >> 3) & 1)*8;   // + m0 + mf*16
    int a_kb  = l >> 4;
    int b_row = (l & 7) + (l >> 4)*8;         // + n0 + nf2*16
    int b_kb  = (l >> 3) & 1;
    int brow = t >> 2, bq2 = (t & 3)*2;       // B: 4 thr/row x 2 uint4

    for (int kc=0; kc<9; kc++){
        __syncthreads();
        // ---- gather 16 px per warp; lane covers channels 2l, 2l+1
        #pragma unroll
        for (int j=0;j<16;j++){
            int px = w*16 + j;
            size_t pk = (size_t)(p0+px)*9 + kc;
            float4 wq = __ldg(&g_cw4[pk]);
            int4   iq = __ldg(&g_ci4[pk]);
            ull v;
            v = f2fma(pk2(wq.x,wq.x), ldg2(xtb + (size_t)iq.x*CC + 2*l), 0ull);
            v = f2fma(pk2(wq.y,wq.y), ldg2(xtb + (size_t)iq.y*CC + 2*l), v);
            v = f2fma(pk2(wq.z,wq.z), ldg2(xtb + (size_t)iq.z*CC + 2*l), v);
            v = f2fma(pk2(wq.w,wq.w), ldg2(xtb + (size_t)iq.w*CC + 2*l), v);
            uint32_t ph, pl; cvt_hilo(v, ph, pl);
            wA[px*36 + l]        = ph;     // 144B rows, conflict-free
            wA[4608 + px*36 + l] = pl;
        }
        // ---- load B hi/lo (64 rows x 128B each)
        {
            const uint4* gBh = (const uint4*)(g_Wbh + (size_t)kc*4096 + brow*64);
            const uint4* gBl = (const uint4*)(g_Wbl + (size_t)kc*4096 + brow*64);
            #pragma unroll
            for (int u=0;u<2;u++){
                smem[2304 + brow*9 + bq2 + u] = __ldg(gBh + bq2 + u);
                smem[2880 + brow*9 + bq2 + u] = __ldg(gBl + bq2 + u);
            }
        }
        __syncthreads();

        // ---- HMMA 3-pass, 32px x 32o warp tile
        #pragma unroll
        for (int ks=0; ks<4; ks++){
            uint32_t ah[2][4], al[2][4], bh[2][4], bl[2][4];
            #pragma unroll
            for (int mf=0; mf<2; mf++){
                uint32_t off = (uint32_t)((m0 + mf*16 + a_row)*9 + ks*2 + a_kb)*16u;
                ldsm4(ah[mf], aBase  + off);
                ldsm4(al[mf], alBase + off);
            }
            #pragma unroll
            for (int nf2=0; nf2<2; nf2++){
                uint32_t off = (uint32_t)((n0 + nf2*16 + b_row)*9 + ks*2 + b_kb)*16u;
                ldsm4(bh[nf2], bhBase + off);
                ldsm4(bl[nf2], blBase + off);
            }
            #pragma unroll
            for (int mf=0; mf<2; mf++){
                #pragma unroll
                for (int nf=0; nf<4; nf++){
                    uint32_t h0 = bh[nf>>1][(nf&1)*2], h1 = bh[nf>>1][(nf&1)*2+1];
                    uint32_t l0 = bl[nf>>1][(nf&1)*2], l1 = bl[nf>>1][(nf&1)*2+1];
                    hmma(acc[mf][nf], ah[mf], h0, h1);   // hi*hi
                    hmma(acc[mf][nf], ah[mf], l0, l1);   // hi*lo
                    hmma(acc[mf][nf], al[mf], h0, h1);   // lo*hi
                }
            }
        }
    }

    // ---- epilogue: stage [o][px pad132], coalesced float4 stores -------------
    __syncthreads();
    float* st = (float*)smem;   // 64*132*4 = 33792 B
    {
        int group = l >> 2, tid4 = l & 3;
        #pragma unroll
        for (int mf=0; mf<2; mf++){
            int r0 = m0 + mf*16 + group;
            #pragma unroll
            for (int nf=0; nf<4; nf++){
                int o = n0 + nf*8 + 2*tid4;
                st[(size_t)o    *132 + r0    ] = acc[mf][nf][0];
                st[(size_t)(o+1)*132 + r0    ] = acc[mf][nf][1];
                st[(size_t)o    *132 + r0 + 8] = acc[mf][nf][2];
                st[(size_t)(o+1)*132 + r0 + 8] = acc[mf][nf][3];
            }
        }
    }
    __syncthreads();
    #pragma unroll
    for (int q=0;q<8;q++){
        int o = q*8 + w;
        float4 v = *(float4*)&st[(size_t)o*132 + 4*l];
        *(float4*)(out + ((size_t)(b*OO + o))*HWSZ + hw0 + 4*l) = v;
    }
}

// ---------------- launch ------------------------------------------------------
extern "C" void kernel_launch(void* const* d_in, const int* in_sizes, int n_in,
                              void* d_out, int out_size){
    const float* x        = (const float*)d_in[0];
    const float* w_main   = (const float*)d_in[1];
    const float* w_offset = (const float*)d_in[2];
    const float* b_offset = (const float*)d_in[3];
    const float* w_mask   = (const float*)d_in[4];
    const float* b_mask   = (const float*)d_in[5];
    float* out = (float*)d_out;

    // idempotent, deterministic: set every call (no static guards)
    cudaFuncSetAttribute(k_fuse, cudaFuncAttributeMaxDynamicSharedMemorySize,
                         FUSE_SMEM);

    int prep_n = 9*64*64 + 9*32*64;
    k_prep<<<(prep_n + TPB-1)/TPB, TPB>>>(w_main, w_offset, w_mask);
    dim3 gx(HWSZ/32, CC/32, BB);
    k_xt<<<gx, dim3(32,8)>>>(x);
    k_om<<<NPIX/128, TPB>>>(b_offset, b_mask);
    k_fuse<<<NPIX/128, TPB, FUSE_SMEM>>>(out);
}

// round 17
// speedup vs baseline: 1.2601x; 1.2423x over previous
#include <cuda_runtime.h>
#include <cuda_bf16.h>
#include <math.h>
#include <stdint.h>

#define BB 8
#define CC 64
#define OO 64
#define HH 128
#define WW 128
#define HWSZ (HH*WW)            // 16384
#define NPIX (BB*HWSZ)          // 131072
#define TPB 256

typedef unsigned long long ull;

// ---------------- scratch (allocation-free: __device__ globals) --------------
__device__ float4         g_cw4[(size_t)NPIX*9];    // per (p,k): 4 corner weights
__device__ int4           g_ci4[(size_t)NPIX*9];    // per (p,k): 4 clamped hw indices
__device__ float          g_xt[(size_t)NPIX*CC];    // [b][hw][c] (33.5 MB, L2-resident)
__device__ unsigned short g_Wf[9*64*64];            // main W fp16: [k][o][c] 128B rows
__device__ __nv_bfloat16  g_OMbh[9*32*64];          // off/mask W hi: [t][j(32)][c]
__device__ __nv_bfloat16  g_OMbl[9*32*64];          // off/mask W lo

// ---------------- packed f32x2 helpers ---------------------------------------
__device__ __forceinline__ ull pk2(float lo, float hi){
    ull r; asm("mov.b64 %0, {%1,%2};" : "=l"(r) : "f"(lo), "f"(hi)); return r;
}
__device__ __forceinline__ void upk2(ull v, float& lo, float& hi){
    asm("mov.b64 {%0,%1}, %2;" : "=f"(lo), "=f"(hi) : "l"(v));
}
__device__ __forceinline__ ull f2fma(ull a, ull b, ull c){
    ull d; asm("fma.rn.f32x2 %0, %1, %2, %3;" : "=l"(d) : "l"(a), "l"(b), "l"(c)); return d;
}
__device__ __forceinline__ ull ldg2(const float* p){
    ull v; asm("ld.global.nc.b64 %0, [%1];" : "=l"(v) : "l"(p)); return v;
}
__device__ __forceinline__ uint32_t smem_u32(const void* p){
    uint32_t a;
    asm("{ .reg .u64 t; cvta.to.shared.u64 t, %1; cvt.u32.u64 %0, t; }" : "=r"(a) : "l"(p));
    return a;
}
__device__ __forceinline__ void ldsm4(uint32_t* r, uint32_t addr){
    asm volatile("ldmatrix.sync.aligned.m8n8.x4.shared.b16 {%0,%1,%2,%3}, [%4];"
        : "=r"(r[0]), "=r"(r[1]), "=r"(r[2]), "=r"(r[3]) : "r"(addr));
}
__device__ __forceinline__ void hmma_bf(float* d, const uint32_t* a, uint32_t b0, uint32_t b1){
    asm volatile("mma.sync.aligned.m16n8k16.row.col.f32.bf16.bf16.f32 "
        "{%0,%1,%2,%3}, {%4,%5,%6,%7}, {%8,%9}, {%0,%1,%2,%3};"
        : "+f"(d[0]), "+f"(d[1]), "+f"(d[2]), "+f"(d[3])
        : "r"(a[0]), "r"(a[1]), "r"(a[2]), "r"(a[3]), "r"(b0), "r"(b1));
}
__device__ __forceinline__ void hmma_f16(float* d, const uint32_t* a, uint32_t b0, uint32_t b1){
    asm volatile("mma.sync.aligned.m16n8k16.row.col.f32.f16.f16.f32 "
        "{%0,%1,%2,%3}, {%4,%5,%6,%7}, {%8,%9}, {%0,%1,%2,%3};"
        : "+f"(d[0]), "+f"(d[1]), "+f"(d[2]), "+f"(d[3])
        : "r"(a[0]), "r"(a[1]), "r"(a[2]), "r"(a[3]), "r"(b0), "r"(b1));
}
// packed fp32x2 -> bf16x2 hi + bf16x2 lo (residual), 6 instrs
__device__ __forceinline__ void cvt_hilo_bf(ull v, uint32_t& ph, uint32_t& pl){
    float f0,f1; upk2(v,f0,f1);
    asm("cvt.rn.bf16x2.f32 %0, %1, %2;" : "=r"(ph) : "f"(f1), "f"(f0));
    uint32_t h0b = ph<<16, h1b = ph & 0xffff0000u;
    ull hp;  asm("mov.b64 %0, {%1,%2};" : "=l"(hp) : "r"(h0b), "r"(h1b));
    ull lo2; asm("sub.rn.f32x2 %0, %1, %2;" : "=l"(lo2) : "l"(v), "l"(hp));
    float g0,g1; upk2(lo2,g0,g1);
    asm("cvt.rn.bf16x2.f32 %0, %1, %2;" : "=r"(pl) : "f"(g1), "f"(g0));
}
// packed fp32x2 -> fp16x2 hi + fp16x2 lo (residual), 6-8 instrs (packed path)
__device__ __forceinline__ void cvt_hilo_f16(ull v, uint32_t& ph, uint32_t& pl){
    float f0,f1; upk2(v,f0,f1);
    asm("cvt.rn.f16x2.f32 %0, %1, %2;" : "=r"(ph) : "f"(f1), "f"(f0));
    float h0, h1;
    asm("{ .reg .b16 x, y; mov.b32 {x, y}, %2; cvt.f32.f16 %0, x; cvt.f32.f16 %1, y; }"
        : "=f"(h0), "=f"(h1) : "r"(ph));
    ull hp = pk2(h0, h1);
    ull lo2; asm("sub.rn.f32x2 %0, %1, %2;" : "=l"(lo2) : "l"(v), "l"(hp));
    float g0,g1; upk2(lo2,g0,g1);
    asm("cvt.rn.f16x2.f32 %0, %1, %2;" : "=r"(pl) : "f"(g1), "f"(g0));
}

// ---------------- prep: main W fp16; off/mask W bf16 hi/lo --------------------
__global__ void k_prep(const float* __restrict__ wm,
                       const float* __restrict__ wo,
                       const float* __restrict__ wk){
    int i = blockIdx.x*TPB + threadIdx.x;
    if (i < 9*64*64){
        int k = i >> 12; int o = (i >> 6) & 63; int c = i & 63;
        float w = wm[(o*CC + c)*9 + k];
        unsigned short hw_;
        asm("{ .reg .b16 x; cvt.rn.f16.f32 x, %1; mov.b16 %0, x; }" : "=h"(hw_) : "f"(w));
        g_Wf[i] = hw_;
    }
    int j2 = i - 9*64*64;
    if (j2 >= 0 && j2 < 9*32*64){
        int tp = j2 >> 11; int j = (j2 >> 6) & 31; int c = j2 & 63;
        float v = 0.f;
        if (j < 18)      v = wo[(j*CC + c)*9 + tp];
        else if (j < 27) v = wk[((j-18)*CC + c)*9 + tp];
        __nv_bfloat16 h = __float2bfloat16(v);
        float r = v - __bfloat162float(h);
        g_OMbh[j2] = h;
        g_OMbl[j2] = __float2bfloat16(r);
    }
}

// ---------------- P0: x [b][c][hw] -> g_xt [b][hw][c] -------------------------
__global__ void k_xt(const float* __restrict__ x){
    __shared__ float t[32][33];
    int b  = blockIdx.z;
    int c0 = blockIdx.y*32;
    int hw0= blockIdx.x*32;
    const float* xb = x + ((size_t)b*CC + c0)*HWSZ + hw0;
    for (int i = threadIdx.y; i < 32; i += 8)
        t[i][threadIdx.x] = xb[(size_t)i*HWSZ + threadIdx.x];
    __syncthreads();
    float* xtb = g_xt + ((size_t)b*HWSZ + hw0)*CC + c0;
    for (int i = threadIdx.y; i < 32; i += 8)
        xtb[(size_t)i*CC + threadIdx.x] = t[threadIdx.x][i];
}

// ---- P1: offset+mask conv as bf16 HMMA GEMM (R14, proven) -------------------
__global__ void __launch_bounds__(TPB)
k_om(const float* __restrict__ boff, const float* __restrict__ bmsk){
    __shared__ __align__(16) uint4 smem[2880];   // 46080 B
    uint32_t* wA = (uint32_t*)smem;

    int t = threadIdx.x, l = t & 31, w = t >> 5;
    int p0 = blockIdx.x*128;
    int b  = p0 >> 14;
    const float* xtb = g_xt + (size_t)b*HWSZ*CC;

    int m0 = (w >> 1)*32;
    int n0 = (w & 1)*16;

    uint32_t aBase = smem_u32(smem);

    float acc[2][2][4];
    #pragma unroll
    for (int i=0;i<2;i++)
        #pragma unroll
        for (int j=0;j<2;j++)
            #pragma unroll
            for (int q=0;q<4;q++) acc[i][j][q] = 0.f;

    int a_row = (l & 7) + ((l >> 3) & 1)*8;
    int a_kb  = l >> 4;
    int b_row = (l & 7) + (l >> 4)*8;
    int b_kb  = (l >> 3) & 1;
    int brow = t >> 3, bu = t & 7;

    for (int tap=0; tap<9; tap++){
        __syncthreads();
        smem[2304 + brow*9 + bu] = __ldg((const uint4*)(g_OMbh + (size_t)tap*2048 + brow*64) + bu);
        smem[2592 + brow*9 + bu] = __ldg((const uint4*)(g_OMbl + (size_t)tap*2048 + brow*64) + bu);
        int dh = tap/3 - 1, dw = tap%3 - 1;
        #pragma unroll
        for (int j=0;j<16;j++){
            int px = w*16 + j;
            int hw = (p0 + px) & (HWSZ-1);
            int h = hw >> 7, wc = hw & (WW-1);
            ull v = 0ull;
            if ((unsigned)(h+dh) < HH && (unsigned)(wc+dw) < WW)
                v = ldg2(xtb + (size_t)(hw + dh*WW + dw)*CC + 2*l);
            uint32_t ph, pl; cvt_hilo_bf(v, ph, pl);
            wA[px*36 + l]        = ph;
            wA[4608 + px*36 + l] = pl;
        }
        __syncthreads();

        #pragma unroll
        for (int ks=0; ks<4; ks++){
            uint32_t ah[2][4], al[2][4], bh[4], bl[4];
            #pragma unroll
            for (int mf=0; mf<2; mf++){
                uint32_t offA = (uint32_t)((m0 + mf*16 + a_row)*9 + ks*2 + a_kb)*16u;
                ldsm4(ah[mf], aBase + offA);
                ldsm4(al[mf], aBase + 18432u + offA);
            }
            {
                uint32_t offB = (uint32_t)((n0 + b_row)*9 + ks*2 + b_kb)*16u;
                ldsm4(bh, aBase + 36864u + offB);
                ldsm4(bl, aBase + 41472u + offB);
            }
            #pragma unroll
            for (int mf=0; mf<2; mf++){
                #pragma unroll
                for (int nf=0; nf<2; nf++){
                    hmma_bf(acc[mf][nf], ah[mf], bh[nf*2], bh[nf*2+1]);
                    hmma_bf(acc[mf][nf], ah[mf], bl[nf*2], bl[nf*2+1]);
                    hmma_bf(acc[mf][nf], al[mf], bh[nf*2], bh[nf*2+1]);
                }
            }
        }
    }

    __syncthreads();
    float* st = (float*)smem;
    {
        int group = l >> 2, tid4 = l & 3;
        #pragma unroll
        for (int mf=0; mf<2; mf++){
            int r0 = m0 + mf*16 + group;
            #pragma unroll
            for (int nf=0; nf<2; nf++){
                int o = n0 + nf*8 + 2*tid4;
                if (o < 28){
                    st[r0*28 + o]       = acc[mf][nf][0];
                    st[r0*28 + o+1]     = acc[mf][nf][1];
                    st[(r0+8)*28 + o]   = acc[mf][nf][2];
                    st[(r0+8)*28 + o+1] = acc[mf][nf][3];
                }
            }
        }
    }
    __syncthreads();
    if (t < 128){
        int p  = p0 + t;
        int hw = p & (HWSZ-1);
        int h  = hw >> 7;
        int wp = hw & (WW-1);
        const float* row = st + t*28;
        #pragma unroll
        for (int k=0;k<9;k++){
            float dy   = row[2*k]   + boff[2*k];
            float dx   = row[2*k+1] + boff[2*k+1];
            float mraw = row[18+k]  + bmsk[k];
            float mk = 1.f/(1.f + expf(-mraw));

            float py = dy + (float)(h + k/3 - 1);
            float px = dx + (float)(wp + k%3 - 1);
            float y0f = floorf(py), x0f = floorf(px);
            float ly = py - y0f, lx = px - x0f;
            int y0 = (int)y0f, x0 = (int)x0f;
            int y1 = y0 + 1,   x1 = x0 + 1;

            float vy0 = (y0>=0 && y0<HH) ? 1.f : 0.f;
            float vy1 = (y1>=0 && y1<HH) ? 1.f : 0.f;
            float vx0 = (x0>=0 && x0<WW) ? 1.f : 0.f;
            float vx1 = (x1>=0 && x1<WW) ? 1.f : 0.f;

            float w00 = (1.f-ly)*(1.f-lx)*vy0*vx0*mk;
            float w01 = (1.f-ly)*lx      *vy0*vx1*mk;
            float w10 = ly      *(1.f-lx)*vy1*vx0*mk;
            float w11 = ly      *lx      *vy1*vx1*mk;

            int y0c = min(max(y0,0),HH-1), y1c = min(max(y1,0),HH-1);
            int x0c = min(max(x0,0),WW-1), x1c = min(max(x1,0),WW-1);

            g_cw4[(size_t)p*9 + k] = make_float4(w00,w01,w10,w11);
            g_ci4[(size_t)p*9 + k] = make_int4(y0c*WW+x0c, y0c*WW+x1c,
                                               y1c*WW+x0c, y1c*WW+x1c);
        }
    }
}

// ---- P2: fused gather + fp16 2-pass HMMA (R14 skeleton, single W tensor) ----
// CTA = 64 px x 64 o, 8 warps (warp tile 32px x 16o). Per k: gather + convert
// fp16 hi/lo into 144B-row smem, then 2-pass HMMA (x_hi*W + x_lo*W).
// smem: Ahi [0,576) | Alo [576,1152) | B [1152,1728) uint4 = 27648 B.
__global__ void __launch_bounds__(TPB)
k_fuse(float* __restrict__ out){
    __shared__ __align__(16) uint4 smem[1728];
    uint4* sBw = smem + 1152;
    uint32_t* wAhi = (uint32_t*)smem;
    uint32_t* wAlo = (uint32_t*)(smem + 576);

    int t = threadIdx.x, l = t & 31, w = t >> 5;
    int p0 = blockIdx.x*64;
    int b  = p0 >> 14;
    int hw0= p0 & (HWSZ-1);
    const float* xtb = g_xt + (size_t)b*HWSZ*CC;

    int m0 = (w & 1)*32;
    int n0 = (w >> 1)*16;

    uint32_t aBase  = smem_u32(smem);
    uint32_t alBase = aBase + 9216u;
    uint32_t bBase  = aBase + 18432u;

    float acc[2][2][4];
    #pragma unroll
    for (int i=0;i<2;i++)
        #pragma unroll
        for (int j=0;j<2;j++)
            #pragma unroll
            for (int q=0;q<4;q++) acc[i][j][q] = 0.f;

    int a_row = (l & 7) + ((l >> 3) & 1)*8;
    int a_kb  = l >> 4;
    int b_row = (l & 7) + (l >> 4)*8;
    int b_kb  = (l >> 3) & 1;
    int brow = t >> 2, bq2 = (t & 3)*2;

    for (int kc=0; kc<9; kc++){
        __syncthreads();
        // ---- gather 8 px per warp; lane covers channels 2l, 2l+1
        #pragma unroll
        for (int j=0;j<8;j++){
            int px = w*8 + j;
            size_t pk = (size_t)(p0+px)*9 + kc;
            float4 wq = __ldg(&g_cw4[pk]);
            int4   iq = __ldg(&g_ci4[pk]);
            ull v;
            v = f2fma(pk2(wq.x,wq.x), ldg2(xtb + (size_t)iq.x*CC + 2*l), 0ull);
            v = f2fma(pk2(wq.y,wq.y), ldg2(xtb + (size_t)iq.y*CC + 2*l), v);
            v = f2fma(pk2(wq.z,wq.z), ldg2(xtb + (size_t)iq.z*CC + 2*l), v);
            v = f2fma(pk2(wq.w,wq.w), ldg2(xtb + (size_t)iq.w*CC + 2*l), v);
            uint32_t ph, pl; cvt_hilo_f16(v, ph, pl);
            wAhi[px*36 + l] = ph;     // 144B rows, conflict-free
            wAlo[px*36 + l] = pl;
        }
        // ---- load B fp16 (64 rows x 128B)
        {
            const uint4* gB = (const uint4*)(g_Wf + (size_t)kc*4096 + brow*64);
            #pragma unroll
            for (int u=0;u<2;u++)
                sBw[brow*9 + bq2 + u] = __ldg(gB + bq2 + u);
        }
        __syncthreads();

        // ---- HMMA: 2-pass fp16
        #pragma unroll
        for (int ks=0; ks<4; ks++){
            uint32_t ah[2][4], al[2][4], bw[4];
            #pragma unroll
            for (int mf=0; mf<2; mf++){
                uint32_t off = (uint32_t)((m0 + mf*16 + a_row)*9 + ks*2 + a_kb)*16u;
                ldsm4(ah[mf], aBase  + off);
                ldsm4(al[mf], alBase + off);
            }
            {
                uint32_t off = (uint32_t)((n0 + b_row)*9 + ks*2 + b_kb)*16u;
                ldsm4(bw, bBase + off);
            }
            #pragma unroll
            for (int mf=0; mf<2; mf++){
                #pragma unroll
                for (int nf=0; nf<2; nf++){
                    hmma_f16(acc[mf][nf], ah[mf], bw[nf*2], bw[nf*2+1]);
                    hmma_f16(acc[mf][nf], al[mf], bw[nf*2], bw[nf*2+1]);
                }
            }
        }
    }

    // ---- epilogue: stage [o][px pad68], coalesced float4 stores --------------
    __syncthreads();
    float* st = (float*)smem;   // 64*68*4 = 17408 B
    {
        int group = l >> 2, tid4 = l & 3;
        #pragma unroll
        for (int mf=0; mf<2; mf++){
            int r0 = m0 + mf*16 + group;
            #pragma unroll
            for (int nf=0; nf<2; nf++){
                int o = n0 + nf*8 + 2*tid4;
                st[(size_t)o    *68 + r0    ] = acc[mf][nf][0];
                st[(size_t)(o+1)*68 + r0    ] = acc[mf][nf][1];
                st[(size_t)o    *68 + r0 + 8] = acc[mf][nf][2];
                st[(size_t)(o+1)*68 + r0 + 8] = acc[mf][nf][3];
            }
        }
    }
    __syncthreads();
    #pragma unroll
    for (int q=0;q<4;q++){
        int o   = q*16 + w*2 + (l >> 4);
        int px4 = (l & 15)*4;
        float4 v = *(float4*)&st[(size_t)o*68 + px4];
        *(float4*)(out + ((size_t)(b*OO + o))*HWSZ + hw0 + px4) = v;
    }
}

// ---------------- launch ------------------------------------------------------
extern "C" void kernel_launch(void* const* d_in, const int* in_sizes, int n_in,
                              void* d_out, int out_size){
    const float* x        = (const float*)d_in[0];
    const float* w_main   = (const float*)d_in[1];
    const float* w_offset = (const float*)d_in[2];
    const float* b_offset = (const float*)d_in[3];
    const float* w_mask   = (const float*)d_in[4];
    const float* b_mask   = (const float*)d_in[5];
    float* out = (float*)d_out;

    int prep_n = 9*64*64 + 9*32*64;
    k_prep<<<(prep_n + TPB-1)/TPB, TPB>>>(w_main, w_offset, w_mask);
    dim3 gx(HWSZ/32, CC/32, BB);
    k_xt<<<gx, dim3(32,8)>>>(x);
    k_om<<<NPIX/128, TPB>>>(b_offset, b_mask);
    k_fuse<<<NPIX/64, TPB>>>(out);
}